// round 5
// baseline (speedup 1.0000x reference)
#include <cuda_runtime.h>
#include <cuda_fp16.h>
#include <cstdint>

#define BN_TOT 2048
#define M_DIM  256
#define CIN    64
#define CMID   256
#define COUT   256
#define W2P    320
#define AP     72            // fp16 smem pitch (144B rows): 8-row ldmatrix group hits banks 0,4..28

// pre-converted fp16 weights (device globals; zero-alloc rule)
__device__ __half g_w1img[256 * AP];    // smem-image layout (pitch AP)
__device__ __half g_w2aimg[256 * AP];   // w2 cols 0..63, smem-image layout
__device__ __half g_w2bh[256 * 256];    // w2 cols 64..319, row-major [o][d]

// ---------------- smem layout (dynamic, bytes) ----------------
#define SX_OFF    0            // 256 rows x AP fp16 = 36864
#define SW1_OFF   36864        // 36864
#define SW2A_OFF  73728        // 36864
#define SMAX_OFF  110592       // 4 x 256 f32 = 4096 (reused as sv[256] later)
#define ZFIN_OFF  114688       // 256 f32 = 1024
#define SMEM_SZ   115712

// ---------------- PTX helpers ----------------
__device__ __forceinline__ unsigned smem_u32(const void* p) {
    return (unsigned)__cvta_generic_to_shared(p);
}
__device__ __forceinline__ void ldm4(unsigned r[4], unsigned addr) {
    asm volatile("ldmatrix.sync.aligned.m8n8.x4.shared.b16 {%0,%1,%2,%3}, [%4];"
                 : "=r"(r[0]), "=r"(r[1]), "=r"(r[2]), "=r"(r[3]) : "r"(addr));
}
__device__ __forceinline__ void mma_f16(float c[4], const unsigned a[4], const unsigned b[2]) {
    asm volatile("mma.sync.aligned.m16n8k16.row.col.f32.f16.f16.f32 "
                 "{%0,%1,%2,%3}, {%4,%5,%6,%7}, {%8,%9}, {%0,%1,%2,%3};"
                 : "+f"(c[0]), "+f"(c[1]), "+f"(c[2]), "+f"(c[3])
                 : "r"(a[0]), "r"(a[1]), "r"(a[2]), "r"(a[3]), "r"(b[0]), "r"(b[1]));
}

// ---------------------------------------------------------------------------
// Prep: build fp16 weight images once (tiny)
// ---------------------------------------------------------------------------
__global__ void prep(const float* __restrict__ w1, const float* __restrict__ w2) {
    int i = blockIdx.x * 256 + threadIdx.x;            // 0..98303
    if (i < 16384) {
        int r = i >> 6, c = i & 63;
        g_w1img[r * AP + c] = __float2half_rn(w1[r * 64 + c]);
    } else if (i < 32768) {
        int j = i - 16384; int r = j >> 6, c = j & 63;
        g_w2aimg[r * AP + c] = __float2half_rn(w2[(size_t)r * W2P + c]);
    } else {
        int j = i - 32768; int o = j >> 8, d = j & 255;
        g_w2bh[o * 256 + d] = __float2half_rn(w2[(size_t)o * W2P + CIN + d]);
    }
}

// ---------------------------------------------------------------------------
// Warp-level 128x128x64 MMA core (verified round-4 layout). warp tile 32m x 64n.
// ---------------------------------------------------------------------------
__device__ __forceinline__ void mma_core(float acc[2][8][4],
                                         const __half* sA, const __half* sB,
                                         int warp_m, int warp_n, int lane) {
    const int lrow = lane & 15, lkh = (lane >> 4) * 8;
#pragma unroll
    for (int ks = 0; ks < 64; ks += 16) {
        unsigned af[2][4];
#pragma unroll
        for (int mi = 0; mi < 2; mi++)
            ldm4(af[mi], smem_u32(sA + (warp_m * 32 + mi * 16 + lrow) * AP + ks + lkh));
        unsigned bf[8][2];
#pragma unroll
        for (int np = 0; np < 4; np++) {
            unsigned t[4];
            ldm4(t, smem_u32(sB + (warp_n * 64 + np * 16 + lrow) * AP + ks + lkh));
            bf[2*np][0]   = t[0]; bf[2*np+1][0] = t[1];
            bf[2*np][1]   = t[2]; bf[2*np+1][1] = t[3];
        }
#pragma unroll
        for (int mi = 0; mi < 2; mi++)
#pragma unroll
            for (int ni = 0; ni < 8; ni++)
                mma_f16(acc[mi][ni], af[mi], bf[ni]);
    }
}

// ---------------------------------------------------------------------------
// Fused per-bn kernel: GEMM1 + max -> v -> GEMM3 + epilogue
// ---------------------------------------------------------------------------
__global__ void __launch_bounds__(256, 2)
fused_bn(const float* __restrict__ x, const float* __restrict__ b1,
         float* __restrict__ out)
{
    extern __shared__ __align__(16) char smem[];
    __half* sX   = (__half*)(smem + SX_OFF);
    __half* sW1  = (__half*)(smem + SW1_OFF);
    __half* sW2a = (__half*)(smem + SW2A_OFF);
    float*  smax = (float*)(smem + SMAX_OFF);   // [4][256]
    float*  sv   = (float*)(smem + SMAX_OFF);   // aliases smax (dead by then)
    float*  zfin = (float*)(smem + ZFIN_OFF);   // [256]

    const int tid = threadIdx.x;
    const int lane = tid & 31, w = tid >> 5;
    const int warp_m = w >> 1, warp_n = w & 1;
    const int bn = blockIdx.x;

    // --- cooperative loads ---
    // weight images: straight uint4 copies (2304 uint4 each)
    {
        const uint4* s1 = (const uint4*)g_w1img;
        const uint4* s2 = (const uint4*)g_w2aimg;
        uint4* d1 = (uint4*)sW1;
        uint4* d2 = (uint4*)sW2a;
#pragma unroll
        for (int i = tid; i < 2304; i += 256) { d1[i] = s1[i]; d2[i] = s2[i]; }
    }
    // x[bn]: 256 rows x 64 fp32 -> fp16, 8 iters, coalesced
    {
        const float* gx = x + (size_t)bn * (M_DIM * CIN);
#pragma unroll
        for (int it = 0; it < 8; it++) {
            int idx = it * 256 + tid;          // 0..2047
            int row = idx >> 3, q = idx & 7;
            const float* p = gx + row * CIN + q * 8;
            float4 v0 = *(const float4*)p;
            float4 v1 = *(const float4*)(p + 4);
            __half2 h0 = __halves2half2(__float2half_rn(v0.x), __float2half_rn(v0.y));
            __half2 h1 = __halves2half2(__float2half_rn(v0.z), __float2half_rn(v0.w));
            __half2 h2 = __halves2half2(__float2half_rn(v1.x), __float2half_rn(v1.y));
            __half2 h3 = __halves2half2(__float2half_rn(v1.z), __float2half_rn(v1.w));
            uint4 u;
            u.x = *(unsigned*)&h0; u.y = *(unsigned*)&h1;
            u.z = *(unsigned*)&h2; u.w = *(unsigned*)&h3;
            *(uint4*)(sX + row * AP + q * 8) = u;
        }
    }
    // init smax
#pragma unroll
    for (int i = tid; i < 1024; i += 256) smax[i] = -3.4e38f;
    __syncthreads();

    // --- GEMM1: z = x @ w1^T, max over m ---
#pragma unroll
    for (int dt = 0; dt < 2; dt++) {
#pragma unroll
        for (int mt = 0; mt < 2; mt++) {
            float acc[2][8][4];
#pragma unroll
            for (int mi = 0; mi < 2; mi++)
#pragma unroll
                for (int ni = 0; ni < 8; ni++)
#pragma unroll
                    for (int c = 0; c < 4; c++) acc[mi][ni][c] = 0.f;

            mma_core(acc, sX + mt * 128 * AP, sW1 + dt * 128 * AP, warp_m, warp_n, lane);

#pragma unroll
            for (int ni = 0; ni < 8; ni++) {
                float m0 = fmaxf(fmaxf(acc[0][ni][0], acc[0][ni][2]),
                                 fmaxf(acc[1][ni][0], acc[1][ni][2]));
                float m1 = fmaxf(fmaxf(acc[0][ni][1], acc[0][ni][3]),
                                 fmaxf(acc[1][ni][1], acc[1][ni][3]));
#pragma unroll
                for (int off = 4; off < 32; off <<= 1) {
                    m0 = fmaxf(m0, __shfl_xor_sync(0xffffffffu, m0, off));
                    m1 = fmaxf(m1, __shfl_xor_sync(0xffffffffu, m1, off));
                }
                if (lane < 4) {
                    int col = dt * 128 + warp_n * 64 + ni * 8 + lane * 2;
                    smax[warp_m * 256 + col]     = fmaxf(smax[warp_m * 256 + col], m0);
                    smax[warp_m * 256 + col + 1] = fmaxf(smax[warp_m * 256 + col + 1], m1);
                }
            }
        }
    }
    __syncthreads();

    // --- zfin = max over 4 warp_m groups + bias ---
    zfin[tid] = fmaxf(fmaxf(smax[tid], smax[256 + tid]),
                      fmaxf(smax[512 + tid], smax[768 + tid])) + b1[tid];
    __syncthreads();

    // --- v[o] = sum_d zfin[d] * w2b[o][d]  (warp per 32 outputs, fp16 w2b) ---
    {
        const float2* zf2 = (const float2*)zfin;
#pragma unroll 4
        for (int oo = 0; oo < 32; oo++) {
            int o = w * 32 + oo;
            const __half2* row = (const __half2*)(g_w2bh + o * 256);
            float acc = 0.f;
#pragma unroll
            for (int i = 0; i < 4; i++) {
                __half2 h = row[i * 32 + lane];
                float2 z = zf2[i * 32 + lane];
                acc = fmaf(z.x, __half2float(__low2half(h)), acc);
                acc = fmaf(z.y, __half2float(__high2half(h)), acc);
            }
#pragma unroll
            for (int off = 16; off > 0; off >>= 1)
                acc += __shfl_xor_sync(0xffffffffu, acc, off);
            if (lane == 0) sv[o] = acc;
        }
    }
    __syncthreads();

    // --- GEMM3: out = x @ w2a^T + v ---
    float* gout = out + (size_t)bn * (M_DIM * COUT);
#pragma unroll
    for (int nt = 0; nt < 2; nt++) {
#pragma unroll
        for (int mt = 0; mt < 2; mt++) {
            float acc[2][8][4];
#pragma unroll
            for (int mi = 0; mi < 2; mi++)
#pragma unroll
                for (int ni = 0; ni < 8; ni++)
#pragma unroll
                    for (int c = 0; c < 4; c++) acc[mi][ni][c] = 0.f;

            mma_core(acc, sX + mt * 128 * AP, sW2a + nt * 128 * AP, warp_m, warp_n, lane);

#pragma unroll
            for (int ni = 0; ni < 8; ni++) {
                int cfrag = warp_n * 64 + ni * 8 + (lane & 3) * 2;
                int col = nt * 128 + cfrag;
                float2 vv = *(const float2*)(sv + nt * 128 + cfrag);
#pragma unroll
                for (int mi = 0; mi < 2; mi++) {
                    int row = mt * 128 + warp_m * 32 + mi * 16 + (lane >> 2);
                    float2 o0v, o1v;
                    o0v.x = acc[mi][ni][0] + vv.x; o0v.y = acc[mi][ni][1] + vv.y;
                    o1v.x = acc[mi][ni][2] + vv.x; o1v.y = acc[mi][ni][3] + vv.y;
                    *(float2*)(gout + (size_t)row * COUT + col)       = o0v;
                    *(float2*)(gout + (size_t)(row + 8) * COUT + col) = o1v;
                }
            }
        }
    }
}

// ---------------------------------------------------------------------------
extern "C" void kernel_launch(void* const* d_in, const int* in_sizes, int n_in,
                              void* d_out, int out_size) {
    const float* x  = (const float*)d_in[0];   // (8,256,256,64)
    const float* w1 = (const float*)d_in[1];   // (256,64)
    const float* b1 = (const float*)d_in[2];   // (256,)
    const float* w2 = (const float*)d_in[3];   // (256,320)
    float* out = (float*)d_out;                // (8,256,256,256)

    static bool attr_set = false;
    if (!attr_set) {
        cudaFuncSetAttribute(fused_bn, cudaFuncAttributeMaxDynamicSharedMemorySize, SMEM_SZ);
        attr_set = true;
    }

    prep<<<384, 256>>>(w1, w2);
    fused_bn<<<BN_TOT, 256, SMEM_SZ>>>(x, b1, out);
}

// round 6
// speedup vs baseline: 1.0449x; 1.0449x over previous
#include <cuda_runtime.h>
#include <cuda_fp16.h>
#include <cstdint>

#define BN_TOT 2048
#define M_DIM  256
#define CIN    64
#define CMID   256
#define COUT   256
#define W2P    320

// byte-offset SW128 swizzle within a tile (rows = 128B)
#define SWZB(o) ((o) ^ (((o) >> 3) & 0x70))

// pre-converted fp16 weights, stored in swizzled tile layout (zero-alloc rule)
__device__ __half g_w1img[256 * 64];    // swizzled image, 32KB
__device__ __half g_w2aimg[256 * 64];   // swizzled image, 32KB
__device__ __half g_w2bh[256 * 256];    // row-major [o][d], 128KB

// ---------------- smem layout (dynamic, bytes) ----------------
#define SX_OFF    0            // 256 rows x 128B = 32768
#define SW_OFF    32768        // 32768 (w1 then w2a)
#define SMAX_OFF  65536        // 4 x 256 f32 = 4096 (aliased as sv later)
#define ZFIN_OFF  69632        // 256 f32 = 1024
#define SMEM_SZ   70656

// ---------------- PTX helpers ----------------
__device__ __forceinline__ unsigned smem_u32(const void* p) {
    return (unsigned)__cvta_generic_to_shared(p);
}
__device__ __forceinline__ void ldm4(unsigned r[4], unsigned addr) {
    asm volatile("ldmatrix.sync.aligned.m8n8.x4.shared.b16 {%0,%1,%2,%3}, [%4];"
                 : "=r"(r[0]), "=r"(r[1]), "=r"(r[2]), "=r"(r[3]) : "r"(addr));
}
__device__ __forceinline__ void mma_f16(float c[4], const unsigned a[4], const unsigned b[2]) {
    asm volatile("mma.sync.aligned.m16n8k16.row.col.f32.f16.f16.f32 "
                 "{%0,%1,%2,%3}, {%4,%5,%6,%7}, {%8,%9}, {%0,%1,%2,%3};"
                 : "+f"(c[0]), "+f"(c[1]), "+f"(c[2]), "+f"(c[3])
                 : "r"(a[0]), "r"(a[1]), "r"(a[2]), "r"(a[3]), "r"(b[0]), "r"(b[1]));
}

// ---------------------------------------------------------------------------
// Prep: build swizzled fp16 weight images + fp16 w2b (tiny, once)
// ---------------------------------------------------------------------------
__global__ void prep(const float* __restrict__ w1, const float* __restrict__ w2) {
    int i = blockIdx.x * 256 + threadIdx.x;            // 0..98303
    if (i < 16384) {
        int r = i >> 6, c = i & 63;
        unsigned o = SWZB((unsigned)(r * 128 + c * 2));
        g_w1img[o >> 1] = __float2half_rn(w1[i]);
    } else if (i < 32768) {
        int j = i - 16384; int r = j >> 6, c = j & 63;
        unsigned o = SWZB((unsigned)(r * 128 + c * 2));
        g_w2aimg[o >> 1] = __float2half_rn(w2[(size_t)r * W2P + c]);
    } else {
        int j = i - 32768; int o = j >> 8, d = j & 255;
        g_w2bh[o * 256 + d] = __float2half_rn(w2[(size_t)o * W2P + CIN + d]);
    }
}

// ---------------------------------------------------------------------------
// Warp-level 128x128x64 MMA core on swizzled tiles. warp tile 32m x 64n.
// baseA/baseB = smem u32 addresses of (row0 of sub-tile).
// ---------------------------------------------------------------------------
__device__ __forceinline__ void mma_core(float acc[2][8][4],
                                         unsigned baseA, unsigned baseB,
                                         int warp_m, int warp_n, int lane) {
    const int lrow = lane & 15;
    const int kb = (lane >> 4) * 16;       // 16B half-select
#pragma unroll
    for (int ks = 0; ks < 64; ks += 16) {
        unsigned af[2][4];
#pragma unroll
        for (int mi = 0; mi < 2; mi++) {
            unsigned o = (unsigned)((warp_m * 32 + mi * 16 + lrow) * 128 + ks * 2 + kb);
            ldm4(af[mi], baseA + SWZB(o));
        }
        unsigned bf[8][2];
#pragma unroll
        for (int np = 0; np < 4; np++) {
            unsigned t[4];
            unsigned o = (unsigned)((warp_n * 64 + np * 16 + lrow) * 128 + ks * 2 + kb);
            ldm4(t, baseB + SWZB(o));
            bf[2*np][0]   = t[0]; bf[2*np+1][0] = t[1];
            bf[2*np][1]   = t[2]; bf[2*np+1][1] = t[3];
        }
#pragma unroll
        for (int mi = 0; mi < 2; mi++)
#pragma unroll
            for (int ni = 0; ni < 8; ni++)
                mma_f16(acc[mi][ni], af[mi], bf[ni]);
    }
}

// ---------------------------------------------------------------------------
// Fused per-bn kernel
// ---------------------------------------------------------------------------
__global__ void __launch_bounds__(256, 2)
fused_bn(const float* __restrict__ x, const float* __restrict__ b1,
         float* __restrict__ out)
{
    extern __shared__ __align__(16) char smem[];
    float* smax = (float*)(smem + SMAX_OFF);   // [4][256]
    float* sv   = (float*)(smem + SMAX_OFF);   // aliases smax (dead by then)
    float* zfin = (float*)(smem + ZFIN_OFF);

    const int tid = threadIdx.x;
    const int lane = tid & 31, w = tid >> 5;
    const int warp_m = w >> 1, warp_n = w & 1;
    const int bn = blockIdx.x;

    const unsigned sxb = smem_u32(smem + SX_OFF);
    const unsigned swb = smem_u32(smem + SW_OFF);

    // --- load w1 image (straight copy preserves swizzle) ---
    {
        const uint4* s1 = (const uint4*)g_w1img;
        uint4* d1 = (uint4*)(smem + SW_OFF);
#pragma unroll
        for (int i = tid; i < 2048; i += 256) d1[i] = s1[i];
    }
    // --- x[bn]: 256 rows x 64 fp32 -> fp16 swizzled, coalesced ---
    {
        const float* gx = x + (size_t)bn * (M_DIM * CIN);
        __half* sX = (__half*)(smem + SX_OFF);
#pragma unroll
        for (int it = 0; it < 8; it++) {
            int idx = it * 256 + tid;          // 0..2047
            int row = idx >> 3, q = idx & 7;
            const float* p = gx + row * CIN + q * 8;
            float4 v0 = *(const float4*)p;
            float4 v1 = *(const float4*)(p + 4);
            __half2 h0 = __halves2half2(__float2half_rn(v0.x), __float2half_rn(v0.y));
            __half2 h1 = __halves2half2(__float2half_rn(v0.z), __float2half_rn(v0.w));
            __half2 h2 = __halves2half2(__float2half_rn(v1.x), __float2half_rn(v1.y));
            __half2 h3 = __halves2half2(__float2half_rn(v1.z), __float2half_rn(v1.w));
            uint4 u;
            u.x = *(unsigned*)&h0; u.y = *(unsigned*)&h1;
            u.z = *(unsigned*)&h2; u.w = *(unsigned*)&h3;
            unsigned o = SWZB((unsigned)(row * 128 + q * 16));
            *(uint4*)((char*)smem + SX_OFF + o) = u;
        }
    }
#pragma unroll
    for (int i = tid; i < 1024; i += 256) smax[i] = -3.4e38f;
    __syncthreads();

    // --- GEMM1: z = x @ w1^T, running max over m ---
#pragma unroll
    for (int dt = 0; dt < 2; dt++) {
#pragma unroll
        for (int mt = 0; mt < 2; mt++) {
            float acc[2][8][4];
#pragma unroll
            for (int mi = 0; mi < 2; mi++)
#pragma unroll
                for (int ni = 0; ni < 8; ni++)
#pragma unroll
                    for (int c = 0; c < 4; c++) acc[mi][ni][c] = 0.f;

            mma_core(acc, sxb + mt * (128 * 128), swb + dt * (128 * 128),
                     warp_m, warp_n, lane);

#pragma unroll
            for (int ni = 0; ni < 8; ni++) {
                float m0 = fmaxf(fmaxf(acc[0][ni][0], acc[0][ni][2]),
                                 fmaxf(acc[1][ni][0], acc[1][ni][2]));
                float m1 = fmaxf(fmaxf(acc[0][ni][1], acc[0][ni][3]),
                                 fmaxf(acc[1][ni][1], acc[1][ni][3]));
#pragma unroll
                for (int off = 4; off < 32; off <<= 1) {
                    m0 = fmaxf(m0, __shfl_xor_sync(0xffffffffu, m0, off));
                    m1 = fmaxf(m1, __shfl_xor_sync(0xffffffffu, m1, off));
                }
                if (lane < 4) {
                    int col = dt * 128 + warp_n * 64 + ni * 8 + lane * 2;
                    smax[warp_m * 256 + col]     = fmaxf(smax[warp_m * 256 + col], m0);
                    smax[warp_m * 256 + col + 1] = fmaxf(smax[warp_m * 256 + col + 1], m1);
                }
            }
        }
    }
    __syncthreads();

    // --- zfin = max over 4 warp_m groups + bias ---
    float zf = fmaxf(fmaxf(smax[tid], smax[256 + tid]),
                     fmaxf(smax[512 + tid], smax[768 + tid])) + b1[tid];
    __syncthreads();           // smax reads done before sv alias is written
    zfin[tid] = zf;

    // --- refill sW with w2a image (GEMM1 fully consumed sW) ---
    {
        const uint4* s2 = (const uint4*)g_w2aimg;
        uint4* d2 = (uint4*)(smem + SW_OFF);
#pragma unroll
        for (int i = tid; i < 2048; i += 256) d2[i] = s2[i];
    }
    __syncthreads();

    // --- v[o] = sum_d zfin[d] * w2b[o][d]  (warp per 32 outputs) ---
    {
        const float2* zf2 = (const float2*)zfin;
#pragma unroll 4
        for (int oo = 0; oo < 32; oo++) {
            int o = w * 32 + oo;
            const __half2* row = (const __half2*)(g_w2bh + o * 256);
            float acc = 0.f;
#pragma unroll
            for (int i = 0; i < 4; i++) {
                __half2 h = row[i * 32 + lane];
                float2 z = zf2[i * 32 + lane];
                acc = fmaf(z.x, __half2float(__low2half(h)), acc);
                acc = fmaf(z.y, __half2float(__high2half(h)), acc);
            }
#pragma unroll
            for (int off = 16; off > 0; off >>= 1)
                acc += __shfl_xor_sync(0xffffffffu, acc, off);
            if (lane == 0) sv[o] = acc;
        }
    }
    __syncthreads();

    // --- GEMM3: out = x @ w2a^T + v ---
    float* gout = out + (size_t)bn * (M_DIM * COUT);
#pragma unroll
    for (int nt = 0; nt < 2; nt++) {
#pragma unroll
        for (int mt = 0; mt < 2; mt++) {
            float acc[2][8][4];
#pragma unroll
            for (int mi = 0; mi < 2; mi++)
#pragma unroll
                for (int ni = 0; ni < 8; ni++)
#pragma unroll
                    for (int c = 0; c < 4; c++) acc[mi][ni][c] = 0.f;

            mma_core(acc, sxb + mt * (128 * 128), swb + nt * (128 * 128),
                     warp_m, warp_n, lane);

#pragma unroll
            for (int ni = 0; ni < 8; ni++) {
                int cfrag = warp_n * 64 + ni * 8 + (lane & 3) * 2;
                int col = nt * 128 + cfrag;
                float2 vv = *(const float2*)(sv + nt * 128 + cfrag);
#pragma unroll
                for (int mi = 0; mi < 2; mi++) {
                    int row = mt * 128 + warp_m * 32 + mi * 16 + (lane >> 2);
                    float2 o0v, o1v;
                    o0v.x = acc[mi][ni][0] + vv.x; o0v.y = acc[mi][ni][1] + vv.y;
                    o1v.x = acc[mi][ni][2] + vv.x; o1v.y = acc[mi][ni][3] + vv.y;
                    *(float2*)(gout + (size_t)row * COUT + col)       = o0v;
                    *(float2*)(gout + (size_t)(row + 8) * COUT + col) = o1v;
                }
            }
        }
    }
}

// ---------------------------------------------------------------------------
extern "C" void kernel_launch(void* const* d_in, const int* in_sizes, int n_in,
                              void* d_out, int out_size) {
    const float* x  = (const float*)d_in[0];   // (8,256,256,64)
    const float* w1 = (const float*)d_in[1];   // (256,64)
    const float* b1 = (const float*)d_in[2];   // (256,)
    const float* w2 = (const float*)d_in[3];   // (256,320)
    float* out = (float*)d_out;                // (8,256,256,256)

    static bool attr_set = false;
    if (!attr_set) {
        cudaFuncSetAttribute(fused_bn, cudaFuncAttributeMaxDynamicSharedMemorySize, SMEM_SZ);
        attr_set = true;
    }

    prep<<<384, 256>>>(w1, w2);
    fused_bn<<<BN_TOT, 256, SMEM_SZ>>>(x, b1, out);
}

// round 7
// speedup vs baseline: 1.0600x; 1.0145x over previous
#include <cuda_runtime.h>
#include <cuda_fp16.h>
#include <cstdint>

#define BN_TOT 2048
#define M_DIM  256
#define CIN    64
#define CMID   256
#define COUT   256
#define W2P    320

// byte-offset SW128 swizzle within a 128B-row tile (verified round 6)
#define SWZB(o) ((o) ^ (((o) >> 3) & 0x70))

// pre-converted fp16 weights (zero-alloc rule)
__device__ __half g_w1img[256 * 64];    // swizzled image (256 rows x 128B), 32KB
__device__ __half g_w2aimg[256 * 64];   // w2 cols 0..63, swizzled image, 32KB
__device__ __half g_w2bT[256 * 256];    // TRANSPOSED [k][o], fp16, 128KB

// final zmax (+bias), produced by K1, consumed by K3
__device__ float g_zmax[BN_TOT * CMID]; // 2MB

// ---------------- PTX helpers ----------------
__device__ __forceinline__ unsigned smem_u32(const void* p) {
    return (unsigned)__cvta_generic_to_shared(p);
}
__device__ __forceinline__ void ldm4(unsigned r[4], unsigned addr) {
    asm volatile("ldmatrix.sync.aligned.m8n8.x4.shared.b16 {%0,%1,%2,%3}, [%4];"
                 : "=r"(r[0]), "=r"(r[1]), "=r"(r[2]), "=r"(r[3]) : "r"(addr));
}
__device__ __forceinline__ void mma_f16(float c[4], const unsigned a[4], const unsigned b[2]) {
    asm volatile("mma.sync.aligned.m16n8k16.row.col.f32.f16.f16.f32 "
                 "{%0,%1,%2,%3}, {%4,%5,%6,%7}, {%8,%9}, {%0,%1,%2,%3};"
                 : "+f"(c[0]), "+f"(c[1]), "+f"(c[2]), "+f"(c[3])
                 : "r"(a[0]), "r"(a[1]), "r"(a[2]), "r"(a[3]), "r"(b[0]), "r"(b[1]));
}

// ---------------------------------------------------------------------------
// Prep: swizzled fp16 weight images + transposed fp16 w2b (tiny, once per launch)
// ---------------------------------------------------------------------------
__global__ void prep(const float* __restrict__ w1, const float* __restrict__ w2) {
    int i = blockIdx.x * 256 + threadIdx.x;            // 0..98303
    if (i < 16384) {
        int r = i >> 6, c = i & 63;
        unsigned o = SWZB((unsigned)(r * 128 + c * 2));
        g_w1img[o >> 1] = __float2half_rn(w1[i]);
    } else if (i < 32768) {
        int j = i - 16384; int r = j >> 6, c = j & 63;
        unsigned o = SWZB((unsigned)(r * 128 + c * 2));
        g_w2aimg[o >> 1] = __float2half_rn(w2[(size_t)r * W2P + c]);
    } else {
        int j = i - 32768;                 // 0..65535
        int o = j & 255, d = j >> 8;       // write coalesced in o
        g_w2bT[d * 256 + o] = __float2half_rn(w2[(size_t)o * W2P + CIN + d]);
    }
}

// ---------------------------------------------------------------------------
// Warp-level 128x128x64 MMA core on swizzled tiles (verified round 6).
// warp tile 32m x 64n; baseA/baseB = smem u32 of sub-tile row 0.
// ---------------------------------------------------------------------------
__device__ __forceinline__ void mma_core(float acc[2][8][4],
                                         unsigned baseA, unsigned baseB,
                                         int warp_m, int warp_n, int lane) {
    const int lrow = lane & 15;
    const int kb = (lane >> 4) * 16;
#pragma unroll
    for (int ks = 0; ks < 64; ks += 16) {
        unsigned af[2][4];
#pragma unroll
        for (int mi = 0; mi < 2; mi++) {
            unsigned o = (unsigned)((warp_m * 32 + mi * 16 + lrow) * 128 + ks * 2 + kb);
            ldm4(af[mi], baseA + SWZB(o));
        }
        unsigned bf[8][2];
#pragma unroll
        for (int np = 0; np < 4; np++) {
            unsigned t[4];
            unsigned o = (unsigned)((warp_n * 64 + np * 16 + lrow) * 128 + ks * 2 + kb);
            ldm4(t, baseB + SWZB(o));
            bf[2*np][0]   = t[0]; bf[2*np+1][0] = t[1];
            bf[2*np][1]   = t[2]; bf[2*np+1][1] = t[3];
        }
#pragma unroll
        for (int mi = 0; mi < 2; mi++)
#pragma unroll
            for (int ni = 0; ni < 8; ni++)
                mma_f16(acc[mi][ni], af[mi], bf[ni]);
    }
}

// load x[bn] (256 rows x 64 fp32) -> fp16 swizzled tiles at smem byte 0
__device__ __forceinline__ void load_x_full(char* smem, const float* __restrict__ gx, int tid) {
#pragma unroll
    for (int it = 0; it < 8; it++) {
        int idx = it * 256 + tid;          // 0..2047
        int row = idx >> 3, q = idx & 7;
        const float* p = gx + row * CIN + q * 8;
        float4 v0 = *(const float4*)p;
        float4 v1 = *(const float4*)(p + 4);
        __half2 h0 = __halves2half2(__float2half_rn(v0.x), __float2half_rn(v0.y));
        __half2 h1 = __halves2half2(__float2half_rn(v0.z), __float2half_rn(v0.w));
        __half2 h2 = __halves2half2(__float2half_rn(v1.x), __float2half_rn(v1.y));
        __half2 h3 = __halves2half2(__float2half_rn(v1.z), __float2half_rn(v1.w));
        uint4 u;
        u.x = *(unsigned*)&h0; u.y = *(unsigned*)&h1;
        u.z = *(unsigned*)&h2; u.w = *(unsigned*)&h3;
        *(uint4*)(smem + SWZB((unsigned)(row * 128 + q * 16))) = u;
    }
}

// ---------------------------------------------------------------------------
// K1: grid(BN_TOT). Resident: full x (32KB) + full w1 image (32KB).
// 4 sub-GEMMs (dt,mt); running max over m; writes final zmax (+bias).
// ---------------------------------------------------------------------------
#define K1_SW   32768
#define K1_SMAX 65536
#define K1_SZ   69632

__global__ void __launch_bounds__(256, 2)
k1_gemm_max(const float* __restrict__ x, const float* __restrict__ b1)
{
    extern __shared__ __align__(1024) char smem[];
    float* smax = (float*)(smem + K1_SMAX);    // [4][256]

    const int tid = threadIdx.x;
    const int lane = tid & 31, w = tid >> 5;
    const int warp_m = w >> 1, warp_n = w & 1;
    const int bn = blockIdx.x;

    const unsigned sxb = smem_u32(smem);
    const unsigned swb = smem_u32(smem + K1_SW);

    // w1 image copy (2048 uint4) + x load
    {
        const uint4* s1 = (const uint4*)g_w1img;
        uint4* d1 = (uint4*)(smem + K1_SW);
#pragma unroll
        for (int i = tid; i < 2048; i += 256) d1[i] = s1[i];
    }
    load_x_full(smem, x + (size_t)bn * (M_DIM * CIN), tid);
#pragma unroll
    for (int i = tid; i < 1024; i += 256) smax[i] = -3.4e38f;
    __syncthreads();

#pragma unroll
    for (int dt = 0; dt < 2; dt++) {
#pragma unroll
        for (int mt = 0; mt < 2; mt++) {
            float acc[2][8][4];
#pragma unroll
            for (int mi = 0; mi < 2; mi++)
#pragma unroll
                for (int ni = 0; ni < 8; ni++)
#pragma unroll
                    for (int c = 0; c < 4; c++) acc[mi][ni][c] = 0.f;

            mma_core(acc, sxb + mt * 16384, swb + dt * 16384, warp_m, warp_n, lane);

#pragma unroll
            for (int ni = 0; ni < 8; ni++) {
                float m0 = fmaxf(fmaxf(acc[0][ni][0], acc[0][ni][2]),
                                 fmaxf(acc[1][ni][0], acc[1][ni][2]));
                float m1 = fmaxf(fmaxf(acc[0][ni][1], acc[0][ni][3]),
                                 fmaxf(acc[1][ni][1], acc[1][ni][3]));
#pragma unroll
                for (int off = 4; off < 32; off <<= 1) {
                    m0 = fmaxf(m0, __shfl_xor_sync(0xffffffffu, m0, off));
                    m1 = fmaxf(m1, __shfl_xor_sync(0xffffffffu, m1, off));
                }
                if (lane < 4) {
                    int col = dt * 128 + warp_n * 64 + ni * 8 + lane * 2;
                    smax[warp_m * 256 + col]     = fmaxf(smax[warp_m * 256 + col], m0);
                    smax[warp_m * 256 + col + 1] = fmaxf(smax[warp_m * 256 + col + 1], m1);
                }
            }
        }
    }
    __syncthreads();

    g_zmax[(size_t)bn * CMID + tid] =
        fmaxf(fmaxf(smax[tid], smax[256 + tid]),
              fmaxf(smax[512 + tid], smax[768 + tid])) + b1[tid];
}

// ---------------------------------------------------------------------------
// K3: grid(2 nt, BN_TOT). Computes its own v-slice (folded K2), then
// out = x @ w2a^T + v for 2 row phases.
// ---------------------------------------------------------------------------
#define K3_SW   32768
#define K3_SVP  49152          // 256 f32 partials
#define K3_SV   50176          // 128 f32
#define K3_SZ   50688

__global__ void __launch_bounds__(256, 2)
k3_gemm_out(const float* __restrict__ x, float* __restrict__ out)
{
    extern __shared__ __align__(1024) char smem[];
    float* svp = (float*)(smem + K3_SVP);
    float* sv  = (float*)(smem + K3_SV);

    const int tid = threadIdx.x;
    const int lane = tid & 31, w = tid >> 5;
    const int warp_m = w >> 1, warp_n = w & 1;
    const int nt = blockIdx.x, bn = blockIdx.y;

    const unsigned sxb = smem_u32(smem);
    const unsigned swb = smem_u32(smem + K3_SW);

    // w2a tile copy (1024 uint4) + x load
    {
        const uint4* s2 = (const uint4*)g_w2aimg + nt * 1024;
        uint4* d2 = (uint4*)(smem + K3_SW);
#pragma unroll
        for (int i = tid; i < 1024; i += 256) d2[i] = s2[i];
    }
    load_x_full(smem, x + (size_t)bn * (M_DIM * CIN), tid);

    // v partials: thread t -> output o = t&127, k-half = t>>7
    {
        const int o = tid & 127, kh = tid >> 7;
        const float* zm = g_zmax + (size_t)bn * CMID + kh * 128;
        const __half* wb = g_w2bT + (kh * 128) * 256 + nt * 128 + o;
        float acc = 0.f;
#pragma unroll 8
        for (int k = 0; k < 128; k++)
            acc = fmaf(zm[k], __half2float(wb[(size_t)k * 256]), acc);
        svp[tid] = acc;
    }
    __syncthreads();
    if (tid < 128) sv[tid] = svp[tid] + svp[tid + 128];
    __syncthreads();

    float* gout = out + (size_t)bn * (M_DIM * COUT);
#pragma unroll
    for (int mt = 0; mt < 2; mt++) {
        float acc[2][8][4];
#pragma unroll
        for (int mi = 0; mi < 2; mi++)
#pragma unroll
            for (int ni = 0; ni < 8; ni++)
#pragma unroll
                for (int c = 0; c < 4; c++) acc[mi][ni][c] = 0.f;

        mma_core(acc, sxb + mt * 16384, swb, warp_m, warp_n, lane);

#pragma unroll
        for (int ni = 0; ni < 8; ni++) {
            int cfrag = warp_n * 64 + ni * 8 + (lane & 3) * 2;
            int col = nt * 128 + cfrag;
            float2 vv = *(const float2*)(sv + cfrag);
#pragma unroll
            for (int mi = 0; mi < 2; mi++) {
                int row = mt * 128 + warp_m * 32 + mi * 16 + (lane >> 2);
                float2 o0v, o1v;
                o0v.x = acc[mi][ni][0] + vv.x; o0v.y = acc[mi][ni][1] + vv.y;
                o1v.x = acc[mi][ni][2] + vv.x; o1v.y = acc[mi][ni][3] + vv.y;
                *(float2*)(gout + (size_t)row * COUT + col)       = o0v;
                *(float2*)(gout + (size_t)(row + 8) * COUT + col) = o1v;
            }
        }
    }
}

// ---------------------------------------------------------------------------
extern "C" void kernel_launch(void* const* d_in, const int* in_sizes, int n_in,
                              void* d_out, int out_size) {
    const float* x  = (const float*)d_in[0];   // (8,256,256,64)
    const float* w1 = (const float*)d_in[1];   // (256,64)
    const float* b1 = (const float*)d_in[2];   // (256,)
    const float* w2 = (const float*)d_in[3];   // (256,320)
    float* out = (float*)d_out;                // (8,256,256,256)

    static bool attr_set = false;
    if (!attr_set) {
        cudaFuncSetAttribute(k1_gemm_max, cudaFuncAttributeMaxDynamicSharedMemorySize, K1_SZ);
        cudaFuncSetAttribute(k3_gemm_out, cudaFuncAttributeMaxDynamicSharedMemorySize, K3_SZ);
        attr_set = true;
    }

    prep<<<384, 256>>>(w1, w2);
    k1_gemm_max<<<BN_TOT, 256, K1_SZ>>>(x, b1);
    dim3 g3(2, BN_TOT);
    k3_gemm_out<<<g3, 256, K3_SZ>>>(x, out);
}